// round 1
// baseline (speedup 1.0000x reference)
#include <cuda_runtime.h>
#include <math.h>

#define NN 50000
#define EE 800000
#define BB 64
#define HH 128

// ---------------- scratch (device globals; no allocation allowed) ----------------
__device__ float g_x   [NN * HH];
__device__ float g_x2  [NN * HH];
__device__ float g_agg [NN * HH];
__device__ float g_v   [NN * HH];
__device__ float g_scores[NN * 4];
__device__ float g_pooled[BB * HH];
__device__ float g_U[HH * 4];
__device__ float g_cvec[4];
__device__ int   g_deg[NN];
__device__ int   g_off[NN + 1];
__device__ int   g_cur[NN];
__device__ int   g_col[EE];
__device__ int   g_gstart[BB + 1];

// ---------------- small helpers ----------------
__device__ __forceinline__ float warp_sum(float v) {
#pragma unroll
    for (int o = 16; o > 0; o >>= 1) v += __shfl_xor_sync(0xffffffffu, v, o);
    return v;
}

// ---------------- CSR build ----------------
__global__ void k_init() {
    int i = blockIdx.x * blockDim.x + threadIdx.x;
    if (i < NN) { g_deg[i] = 0; g_cur[i] = 0; }
}

__global__ void k_deg(const int* __restrict__ ei) {
    int e = blockIdx.x * blockDim.x + threadIdx.x;
    if (e < EE) atomicAdd(&g_deg[ei[EE + e]], 1);
}

__global__ void k_scan() {
    __shared__ int sm[1024];
    const int n = NN;
    const int chunk = (n + 1023) / 1024;  // 49
    int t = threadIdx.x;
    int base = t * chunk;
    int s = 0;
    for (int i = 0; i < chunk; ++i) {
        int idx = base + i;
        if (idx < n) s += g_deg[idx];
    }
    sm[t] = s;
    __syncthreads();
    for (int d = 1; d < 1024; d <<= 1) {
        int add = (t >= d) ? sm[t - d] : 0;
        __syncthreads();
        sm[t] += add;
        __syncthreads();
    }
    int run = sm[t] - s;  // exclusive prefix of this chunk
    for (int i = 0; i < chunk; ++i) {
        int idx = base + i;
        if (idx < n) { g_off[idx] = run; run += g_deg[idx]; }
    }
    if (t == 1023) g_off[n] = sm[1023];
}

__global__ void k_fill(const int* __restrict__ ei) {
    int e = blockIdx.x * blockDim.x + threadIdx.x;
    if (e < EE) {
        int s = ei[e];
        int d = ei[EE + e];
        int slot = atomicAdd(&g_cur[d], 1);
        g_col[g_off[d] + slot] = s;
    }
}

// ---------------- neighbor mean aggregation (warp per node) ----------------
__global__ void __launch_bounds__(256) k_aggr(const float* __restrict__ x) {
    int warp = (blockIdx.x * blockDim.x + threadIdx.x) >> 5;
    int lane = threadIdx.x & 31;
    if (warp >= NN) return;
    int s0 = g_off[warp], s1 = g_off[warp + 1];
    float4 a = make_float4(0.f, 0.f, 0.f, 0.f);
    for (int i = s0; i < s1; ++i) {
        int nb = __ldg(&g_col[i]);
        float4 xv = __ldg(reinterpret_cast<const float4*>(x + (size_t)nb * HH) + lane);
        a.x += xv.x; a.y += xv.y; a.z += xv.z; a.w += xv.w;
    }
    float inv = 1.f / fmaxf((float)(s1 - s0), 1.f);
    a.x *= inv; a.y *= inv; a.z *= inv; a.w *= inv;
    reinterpret_cast<float4*>(g_agg + (size_t)warp * HH)[lane] = a;
}

// ---------------- fused GEMM (+bias +relu | +LN +relu +residual) ----------------
// out[n,j] = epilogue( A1[n,:]@W1[j,:] (+ A2[n,:]@W2[j,:]) + bias[j] )
// tile: 64 rows x 128 cols, 256 threads; each thread: 8 rows x 4 cols.
template <bool HAS2, bool RELU, bool DO_LN>
__global__ void __launch_bounds__(256) k_gemm(
    const float* __restrict__ A1, const float* __restrict__ W1,
    const float* __restrict__ A2, const float* __restrict__ W2,
    const float* __restrict__ bias,
    const float* __restrict__ lng, const float* __restrict__ lnb,
    const float* __restrict__ resid,
    float* __restrict__ out, int nrows)
{
    __shared__ float As[64][32];
    __shared__ float Wt[32][128];

    int t = threadIdx.x;
    int tile0 = blockIdx.x * 64;
    int lane = t & 31, wrp = t >> 5;

    float4 acc[8];
#pragma unroll
    for (int i = 0; i < 8; ++i) acc[i] = make_float4(0.f, 0.f, 0.f, 0.f);

    const int NC = HAS2 ? 8 : 4;
    for (int c = 0; c < NC; ++c) {
        const float* Ap = (HAS2 && c >= 4) ? A2 : A1;
        const float* Wp = (HAS2 && c >= 4) ? W2 : W1;
        int kofs = (c & 3) * 32;
        // stage A tile (64 x 32)
#pragma unroll
        for (int m = 0; m < 2; ++m) {
            int i = t + 256 * m;
            int r = i >> 3, q = i & 7;
            int grow = tile0 + r;
            float4 val = make_float4(0.f, 0.f, 0.f, 0.f);
            if (grow < nrows)
                val = *reinterpret_cast<const float4*>(Ap + (size_t)grow * HH + kofs + q * 4);
            *reinterpret_cast<float4*>(&As[r][q * 4]) = val;
        }
        // stage W chunk transposed (32 x 128)
#pragma unroll
        for (int m = 0; m < 4; ++m) {
            int i = t + 256 * m;
            int j = i >> 3, q = i & 7;
            float4 wv = *reinterpret_cast<const float4*>(Wp + (size_t)j * HH + kofs + q * 4);
            Wt[q * 4 + 0][j] = wv.x;
            Wt[q * 4 + 1][j] = wv.y;
            Wt[q * 4 + 2][j] = wv.z;
            Wt[q * 4 + 3][j] = wv.w;
        }
        __syncthreads();
#pragma unroll
        for (int kk = 0; kk < 32; ++kk) {
            float4 w = *reinterpret_cast<const float4*>(&Wt[kk][lane * 4]);
#pragma unroll
            for (int i = 0; i < 8; ++i) {
                float a = As[wrp * 8 + i][kk];
                acc[i].x = fmaf(a, w.x, acc[i].x);
                acc[i].y = fmaf(a, w.y, acc[i].y);
                acc[i].z = fmaf(a, w.z, acc[i].z);
                acc[i].w = fmaf(a, w.w, acc[i].w);
            }
        }
        __syncthreads();
    }

    float4 b4 = *reinterpret_cast<const float4*>(bias + lane * 4);
    if (!DO_LN) {
#pragma unroll
        for (int i = 0; i < 8; ++i) {
            int row = tile0 + wrp * 8 + i;
            if (row < nrows) {
                float4 r;
                r.x = acc[i].x + b4.x; r.y = acc[i].y + b4.y;
                r.z = acc[i].z + b4.z; r.w = acc[i].w + b4.w;
                if (RELU) {
                    r.x = fmaxf(r.x, 0.f); r.y = fmaxf(r.y, 0.f);
                    r.z = fmaxf(r.z, 0.f); r.w = fmaxf(r.w, 0.f);
                }
                *reinterpret_cast<float4*>(out + (size_t)row * HH + lane * 4) = r;
            }
        }
    } else {
        float4 g4  = *reinterpret_cast<const float4*>(lng + lane * 4);
        float4 bb4 = *reinterpret_cast<const float4*>(lnb + lane * 4);
#pragma unroll
        for (int i = 0; i < 8; ++i) {
            int row = tile0 + wrp * 8 + i;
            if (row < nrows) {  // uniform across warp
                float4 h;
                h.x = acc[i].x + b4.x; h.y = acc[i].y + b4.y;
                h.z = acc[i].z + b4.z; h.w = acc[i].w + b4.w;
                float s  = h.x + h.y + h.z + h.w;
                float ss = h.x * h.x + h.y * h.y + h.z * h.z + h.w * h.w;
                s  = warp_sum(s);
                ss = warp_sum(ss);
                float mean = s * (1.f / 128.f);
                float var  = ss * (1.f / 128.f) - mean * mean;
                float rstd = rsqrtf(var + 1e-5f);
                float4 res = *reinterpret_cast<const float4*>(resid + (size_t)row * HH + lane * 4);
                float4 o;
                o.x = fmaxf((h.x - mean) * rstd * g4.x + bb4.x, 0.f) + res.x;
                o.y = fmaxf((h.y - mean) * rstd * g4.y + bb4.y, 0.f) + res.y;
                o.z = fmaxf((h.z - mean) * rstd * g4.z + bb4.z, 0.f) + res.z;
                o.w = fmaxf((h.w - mean) * rstd * g4.w + bb4.w, 0.f) + res.w;
                *reinterpret_cast<float4*>(out + (size_t)row * HH + lane * 4) = o;
            }
        }
    }
}

// ---------------- attention prep: U[k][h] = sum_d q[h,d]*Wk[h*32+d,k]/sqrt(32) ----------------
__global__ void k_prep(const float* __restrict__ in_proj_W,
                       const float* __restrict__ in_proj_b,
                       const float* __restrict__ query) {
    __shared__ float qv[128];
    int t = threadIdx.x;
    float s = in_proj_b[t];
    for (int k = 0; k < 128; ++k) s = fmaf(in_proj_W[t * 128 + k], query[k], s);
    qv[t] = s;
    __syncthreads();
    const float inv = 1.0f / sqrtf(32.0f);
    float u[4] = {0.f, 0.f, 0.f, 0.f};
    for (int r = 0; r < 128; ++r) {
        float w = in_proj_W[(128 + r) * 128 + t];
        u[r >> 5] = fmaf(qv[r], w, u[r >> 5]);
    }
#pragma unroll
    for (int h = 0; h < 4; ++h) g_U[t * 4 + h] = u[h] * inv;
    if (t < 4) {
        float cc = 0.f;
        for (int d = 0; d < 32; ++d) cc = fmaf(qv[t * 32 + d], in_proj_b[128 + t * 32 + d], cc);
        g_cvec[t] = cc * inv;
    }
}

// ---------------- scores = x @ U + c (warp per node) ----------------
__global__ void __launch_bounds__(256) k_scores(const float* __restrict__ x) {
    int warp = (blockIdx.x * blockDim.x + threadIdx.x) >> 5;
    int lane = threadIdx.x & 31;
    if (warp >= NN) return;
    float4 xv = __ldg(reinterpret_cast<const float4*>(x + (size_t)warp * HH) + lane);
    float xs[4] = {xv.x, xv.y, xv.z, xv.w};
    float4 acc = make_float4(0.f, 0.f, 0.f, 0.f);
    const float4* U4 = reinterpret_cast<const float4*>(g_U);
#pragma unroll
    for (int s = 0; s < 4; ++s) {
        float4 u = U4[lane * 4 + s];
        acc.x = fmaf(xs[s], u.x, acc.x);
        acc.y = fmaf(xs[s], u.y, acc.y);
        acc.z = fmaf(xs[s], u.z, acc.z);
        acc.w = fmaf(xs[s], u.w, acc.w);
    }
    acc.x = warp_sum(acc.x); acc.y = warp_sum(acc.y);
    acc.z = warp_sum(acc.z); acc.w = warp_sum(acc.w);
    if (lane == 0) {
        float4 r;
        r.x = acc.x + g_cvec[0]; r.y = acc.y + g_cvec[1];
        r.z = acc.z + g_cvec[2]; r.w = acc.w + g_cvec[3];
        reinterpret_cast<float4*>(g_scores)[warp] = r;
    }
}

// ---------------- graph boundaries from sorted batch ----------------
__global__ void k_gbounds(const int* __restrict__ batch) {
    int i = blockIdx.x * blockDim.x + threadIdx.x;
    if (i >= NN) return;
    int bi = batch[i];
    if (i == 0) {
        for (int g = 0; g <= bi; ++g) g_gstart[g] = 0;
    } else {
        int bp = batch[i - 1];
        for (int g = bp + 1; g <= bi; ++g) g_gstart[g] = i;
    }
    if (i == NN - 1) {
        for (int g = bi + 1; g <= BB; ++g) g_gstart[g] = NN;
    }
}

// ---------------- per-graph segment softmax + weighted V pool ----------------
__global__ void __launch_bounds__(256) k_pool() {
    int b = blockIdx.x;
    int s0 = g_gstart[b], s1 = g_gstart[b + 1];
    int t = threadIdx.x;
    __shared__ float4 red[256];
    __shared__ float smax[4];
    __shared__ float pbuf[256];
    __shared__ float dbuf[8];

    float4 mx = make_float4(-1e30f, -1e30f, -1e30f, -1e30f);
    for (int n = s0 + t; n < s1; n += 256) {
        float4 f = reinterpret_cast<const float4*>(g_scores)[n];
        mx.x = fmaxf(mx.x, f.x); mx.y = fmaxf(mx.y, f.y);
        mx.z = fmaxf(mx.z, f.z); mx.w = fmaxf(mx.w, f.w);
    }
    red[t] = mx;
    __syncthreads();
    for (int s = 128; s > 0; s >>= 1) {
        if (t < s) {
            float4 a = red[t], c = red[t + s];
            a.x = fmaxf(a.x, c.x); a.y = fmaxf(a.y, c.y);
            a.z = fmaxf(a.z, c.z); a.w = fmaxf(a.w, c.w);
            red[t] = a;
        }
        __syncthreads();
    }
    if (t == 0) { smax[0] = red[0].x; smax[1] = red[0].y; smax[2] = red[0].z; smax[3] = red[0].w; }
    __syncthreads();

    int tau = t >> 7, j = t & 127, h = j >> 5;
    float m = smax[h];
    float pl = 0.f, den = 0.f;
    for (int n = s0 + tau; n < s1; n += 2) {
        float e = expf(g_scores[n * 4 + h] - m);
        pl = fmaf(e, g_v[(size_t)n * HH + j], pl);
        den += e;
    }
    pbuf[t] = pl;
    if ((j & 31) == 0) dbuf[tau * 4 + h] = den;
    __syncthreads();
    if (t < 128) {
        float d = dbuf[h] + dbuf[4 + h];
        float p = pbuf[t] + pbuf[128 + t];
        g_pooled[b * HH + t] = (d > 0.f) ? p / d : 0.f;
    }
}

// ---------------- tail: out proj, symbolic processor, fusion, heads ----------------
__device__ __forceinline__ float block_ln128(float v, float gamma, float beta,
                                             float* ws, float* wq) {
    float s = warp_sum(v);
    float q = warp_sum(v * v);
    int wid = threadIdx.x >> 5, lane = threadIdx.x & 31;
    if (lane == 0) { ws[wid] = s; wq[wid] = q; }
    __syncthreads();
    float ts = ws[0] + ws[1] + ws[2] + ws[3];
    float tq = wq[0] + wq[1] + wq[2] + wq[3];
    __syncthreads();
    float mean = ts * (1.f / 128.f);
    float var  = tq * (1.f / 128.f) - mean * mean;
    return (v - mean) * rsqrtf(var + 1e-5f) * gamma + beta;
}

__global__ void __launch_bounds__(128) k_tail(
    const float* __restrict__ out_W, const float* __restrict__ out_b,
    const float* __restrict__ symfeat,
    const float* __restrict__ sym_W, const float* __restrict__ sym_b,
    const float* __restrict__ symf_W, const float* __restrict__ symf_b,
    const float* __restrict__ symf_g, const float* __restrict__ symf_beta,
    const float* __restrict__ fus_W, const float* __restrict__ fus_b,
    const float* __restrict__ fus_g, const float* __restrict__ fus_beta,
    const float* __restrict__ hW1, const float* __restrict__ hb1,
    const float* __restrict__ hW2, const float* __restrict__ hb2,
    float* __restrict__ outp)
{
    int b = blockIdx.x;
    int t = threadIdx.x;
    __shared__ float p[128];
    __shared__ float cat[256];
    __shared__ float buf[128];
    __shared__ float hh[192];
    __shared__ float ws[4], wq[4];

    p[t] = g_pooled[b * HH + t];
    __syncthreads();

    // g = pooled @ out_W^T + out_b  (no activation)
    {
        float acc = out_b[t];
        for (int k = 0; k < 128; ++k) acc = fmaf(out_W[t * 128 + k], p[k], acc);
        cat[t] = acc;
    }
    // symbolic encoders: emb[f][o] = relu(sum_i parts[f][i]*sym_W[f][o][i] + sym_b[f][o])
    {
        int f = t >> 5, o = t & 31;
        const float* sf = symfeat + b * 64 + f * 16;
        const float* w  = sym_W + (f * 32 + o) * 16;
        float s = sym_b[f * 32 + o];
#pragma unroll
        for (int i = 0; i < 16; ++i) s = fmaf(w[i], sf[i], s);
        buf[t] = fmaxf(s, 0.f);
    }
    __syncthreads();
    // sym = LN(relu(emb @ symf_W^T + symf_b))
    {
        float s2 = symf_b[t];
        for (int k = 0; k < 128; ++k) s2 = fmaf(symf_W[t * 128 + k], buf[k], s2);
        s2 = fmaxf(s2, 0.f);
        float v = block_ln128(s2, symf_g[t], symf_beta[t], ws, wq);
        cat[128 + t] = v;
    }
    __syncthreads();
    // fused = LN(relu(cat @ fus_W^T + fus_b))
    {
        float f = fus_b[t];
        for (int k = 0; k < 256; ++k) f = fmaf(fus_W[t * 256 + k], cat[k], f);
        f = fmaxf(f, 0.f);
        float v = block_ln128(f, fus_g[t], fus_beta[t], ws, wq);
        p[t] = v;  // p reused as fused vector
    }
    __syncthreads();
    // heads: hh[k][o] = relu(head_W1[k][o][:] . fused + b1)
    for (int idx = t; idx < 192; idx += 128) {
        int k = idx >> 6, o = idx & 63;
        const float* w = hW1 + (size_t)(k * 64 + o) * 128;
        float acc = hb1[k * 64 + o];
        for (int j = 0; j < 128; ++j) acc = fmaf(w[j], p[j], acc);
        hh[idx] = fmaxf(acc, 0.f);
    }
    __syncthreads();
    if (t < 3) {
        float z = hb2[t];
        for (int o = 0; o < 64; ++o) z = fmaf(hW2[t * 64 + o], hh[t * 64 + o], z);
        outp[t * BB + b] = 1.f / (1.f + expf(-z));
    }
}

// ---------------- host ----------------
extern "C" void kernel_launch(void* const* d_in, const int* in_sizes, int n_in,
                              void* d_out, int out_size) {
    const float* nf = nullptr;
    const float* symf = nullptr;
    const int* ei = nullptr;
    const int* batch = nullptr;
    const float* P[26];
    int pi = 0;
    for (int i = 0; i < n_in; ++i) {
        int sz = in_sizes[i];
        if (sz == NN * HH)       nf    = (const float*)d_in[i];
        else if (sz == BB * 64)  symf  = (const float*)d_in[i];
        else if (sz == 2 * EE)   ei    = (const int*)d_in[i];
        else if (sz == NN)       batch = (const int*)d_in[i];
        else if (pi < 26)        P[pi++] = (const float*)d_in[i];
    }
    const float *W_in = P[0], *b_in = P[1], *sage_Wl = P[2], *sage_bl = P[3],
                *sage_Wr = P[4], *ln_g = P[5], *ln_b = P[6], *query = P[7],
                *in_proj_W = P[8], *in_proj_b = P[9], *out_W = P[10], *out_b = P[11],
                *sym_W = P[12], *sym_b = P[13], *symf_W = P[14], *symf_b = P[15],
                *symf_g = P[16], *symf_beta = P[17], *fus_W = P[18], *fus_b = P[19],
                *fus_g = P[20], *fus_beta = P[21], *hW1 = P[22], *hb1 = P[23],
                *hW2 = P[24], *hb2 = P[25];

    float *px, *px2, *pagg, *pv;
    cudaGetSymbolAddress((void**)&px,   g_x);
    cudaGetSymbolAddress((void**)&px2,  g_x2);
    cudaGetSymbolAddress((void**)&pagg, g_agg);
    cudaGetSymbolAddress((void**)&pv,   g_v);

    const int GEMM_BLOCKS = (NN + 63) / 64;  // 782

    k_init<<<(NN + 255) / 256, 256>>>();
    k_deg<<<(EE + 255) / 256, 256>>>(ei);
    k_scan<<<1, 1024>>>();
    k_fill<<<(EE + 255) / 256, 256>>>(ei);
    k_prep<<<1, 128>>>(in_proj_W, in_proj_b, query);
    k_gbounds<<<(NN + 255) / 256, 256>>>(batch);

    // x = relu(node_features @ W_in^T + b_in)
    k_gemm<false, true, false><<<GEMM_BLOCKS, 256>>>(
        nf, W_in, nullptr, nullptr, b_in, nullptr, nullptr, nullptr, px, NN);

    float* cur = px;
    float* nxt = px2;
    for (int l = 0; l < 3; ++l) {
        k_aggr<<<(NN * 32 + 255) / 256, 256>>>(cur);
        k_gemm<true, false, true><<<GEMM_BLOCKS, 256>>>(
            pagg, sage_Wl + l * 128 * 128, cur, sage_Wr + l * 128 * 128,
            sage_bl + l * 128, ln_g + l * 128, ln_b + l * 128, cur, nxt, NN);
        float* tmp = cur; cur = nxt; nxt = tmp;
    }

    // v = x @ Wv^T + bv   (Wv = in_proj_W rows 256..383)
    k_gemm<false, false, false><<<GEMM_BLOCKS, 256>>>(
        cur, in_proj_W + 256 * 128, nullptr, nullptr, in_proj_b + 256,
        nullptr, nullptr, nullptr, pv, NN);

    k_scores<<<(NN * 32 + 255) / 256, 256>>>(cur);
    k_pool<<<BB, 256>>>();
    k_tail<<<BB, 128>>>(out_W, out_b, symf, sym_W, sym_b,
                        symf_W, symf_b, symf_g, symf_beta,
                        fus_W, fus_b, fus_g, fus_beta,
                        hW1, hb1, hW2, hb2, (float*)d_out);
    (void)out_size;
}

// round 3
// speedup vs baseline: 1.2743x; 1.2743x over previous
#include <cuda_runtime.h>
#include <cuda_bf16.h>
#include <math.h>
#include <stdint.h>

#define NN 50000
#define EE 800000
#define BB 64
#define HH 128
#define TILES 391   // ceil(50000/128)

// ---------------- scratch (device globals) ----------------
__device__ float g_x   [NN * HH];
__device__ float g_x2  [NN * HH];
__device__ float g_agg [NN * HH];
__device__ float g_v   [NN * HH];
__device__ float g_scores[NN * 4];
__device__ float g_pooled[BB * HH];
__device__ float g_U[HH * 4];
__device__ float g_cvec[4];
__device__ int   g_deg[NN];
__device__ int   g_off[NN + 1];
__device__ int   g_cur[NN];
__device__ int   g_col[EE];
__device__ int   g_gstart[BB + 1];
// bf16 hi/lo weight planes: 8 matrices x 64KB (hi 32KB then lo 32KB), plain row-major [n][k]
__device__ uint4 g_wbuf[8 * 4096];

// ---------------- bf16 split helpers ----------------
__device__ __forceinline__ void hilo(float v, uint32_t& h, uint32_t& l) {
    __nv_bfloat16 hb = __float2bfloat16(v);
    __nv_bfloat16 lb = __float2bfloat16(v - __bfloat162float(hb));
    h = (uint32_t)__bfloat16_as_ushort(hb);
    l = (uint32_t)__bfloat16_as_ushort(lb);
}

// ---------------- weight pre-conversion (plain row-major hi/lo planes) ----------------
__global__ void k_wconv(const float* w0, const float* w1, const float* w2, const float* w3,
                        const float* w4, const float* w5, const float* w6, const float* w7) {
    int m = blockIdx.x >> 4;
    const float* W;
    switch (m) {
        case 0: W = w0; break; case 1: W = w1; break; case 2: W = w2; break;
        case 3: W = w3; break; case 4: W = w4; break; case 5: W = w5; break;
        case 6: W = w6; break; default: W = w7; break;
    }
    int i = (blockIdx.x & 15) * 256 + threadIdx.x;  // float4 index 0..4095
    int row = i >> 5, q = i & 31;
    float4 v = *reinterpret_cast<const float4*>(W + (size_t)row * 128 + q * 4);
    uint32_t h0, l0, h1, l1, h2, l2, h3, l3;
    hilo(v.x, h0, l0); hilo(v.y, h1, l1); hilo(v.z, h2, l2); hilo(v.w, h3, l3);
    uint2 uh, ul;
    uh.x = h0 | (h1 << 16); uh.y = h2 | (h3 << 16);
    ul.x = l0 | (l1 << 16); ul.y = l2 | (l3 << 16);
    char* base = (char*)g_wbuf + (size_t)m * 65536;
    int sw = row * 256 + q * 8;
    *reinterpret_cast<uint2*>(base + sw)         = uh;
    *reinterpret_cast<uint2*>(base + 32768 + sw) = ul;
}

// ---------------- HMMA macro ----------------
#define HMMA(C, A0, A1, A2, A3, B0, B1) \
    asm volatile("mma.sync.aligned.m16n8k16.row.col.f32.bf16.bf16.f32 " \
                 "{%0,%1,%2,%3}, {%4,%5,%6,%7}, {%8,%9}, {%0,%1,%2,%3};" \
                 : "+f"((C)[0]), "+f"((C)[1]), "+f"((C)[2]), "+f"((C)[3]) \
                 : "r"(A0), "r"(A1), "r"(A2), "r"(A3), "r"(B0), "r"(B1))

// ---------------- SMEM layout (bytes) ----------------
// A/W tiles: 128 rows x 272B (128 bf16 + 8 pad). Row stride 272 = 68 words (== 4 mod 32 banks)
#define ROWB    272
#define OFF_AH  0
#define OFF_AL  34816
#define OFF_WH  69632
#define OFF_WL  104448
#define OFF_BIAS 139264
#define OFF_G    139776
#define OFF_BETA 140288
#define OFF_MEAN 140800
#define OFF_RSTD 141312
#define SMEM_BYTES 141824
// C spill tile (aliases A region after math): 128 x 129 floats

__device__ __forceinline__ void fill_A(const float* __restrict__ A, char* smem,
                                       int tile0, int nrows, int t) {
    for (int i = t; i < 4096; i += 256) {
        int row = i >> 5, q = i & 31;
        int grow = tile0 + row;
        float4 v = make_float4(0.f, 0.f, 0.f, 0.f);
        if (grow < nrows) v = *reinterpret_cast<const float4*>(A + (size_t)grow * HH + q * 4);
        uint32_t h0, l0, h1, l1, h2, l2, h3, l3;
        hilo(v.x, h0, l0); hilo(v.y, h1, l1); hilo(v.z, h2, l2); hilo(v.w, h3, l3);
        uint2 uh, ul;
        uh.x = h0 | (h1 << 16); uh.y = h2 | (h3 << 16);
        ul.x = l0 | (l1 << 16); ul.y = l2 | (l3 << 16);
        int d = row * ROWB + q * 8;
        *reinterpret_cast<uint2*>(smem + OFF_AH + d) = uh;
        *reinterpret_cast<uint2*>(smem + OFF_AL + d) = ul;
    }
}

__device__ __forceinline__ void fill_W(int slot, char* smem, int t) {
    const char* src = (const char*)g_wbuf + (size_t)slot * 65536;
    for (int i = t; i < 2048; i += 256) {
        int row = i >> 4, q = i & 15;
        int d = row * ROWB + q * 16;
        *reinterpret_cast<uint4*>(smem + OFF_WH + d) =
            *reinterpret_cast<const uint4*>(src + i * 16);
        *reinterpret_cast<uint4*>(smem + OFF_WL + d) =
            *reinterpret_cast<const uint4*>(src + 32768 + i * 16);
    }
}

// EPI: 0 = bias only, 1 = bias+relu, 2 = bias+LN+relu+residual
template <int NPASS, int EPI>
__global__ void __launch_bounds__(256) k_mma(
    const float* __restrict__ A1, const float* __restrict__ A2, int wslot,
    const float* __restrict__ bias,
    const float* __restrict__ lng, const float* __restrict__ lnb,
    const float* __restrict__ resid,
    float* __restrict__ out, int nrows)
{
    extern __shared__ char smem[];
    int t = threadIdx.x, wid = t >> 5, lane = t & 31;
    int tile0 = blockIdx.x * 128;
    int g = lane >> 2, tt = lane & 3;
    int wm = wid & 1, wn = wid >> 1;

    if (t < 128) {
        ((float*)(smem + OFF_BIAS))[t] = bias[t];
        if (EPI == 2) {
            ((float*)(smem + OFF_G))[t]    = lng[t];
            ((float*)(smem + OFF_BETA))[t] = lnb[t];
        }
    }

    float c[4][4][4];
#pragma unroll
    for (int mb = 0; mb < 4; ++mb)
#pragma unroll
        for (int nb = 0; nb < 4; ++nb)
#pragma unroll
            for (int j = 0; j < 4; ++j) c[mb][nb][j] = 0.f;

#pragma unroll
    for (int p = 0; p < NPASS; ++p) {
        fill_A(p ? A2 : A1, smem, tile0, nrows, t);
        fill_W(wslot + p, smem, t);
        __syncthreads();

#pragma unroll
        for (int ks = 0; ks < 8; ++ks) {
            int kb = ks * 16;
            uint32_t bh[4][2], bl[4][2];
#pragma unroll
            for (int nb = 0; nb < 4; ++nb) {
                int n = wn * 32 + nb * 8 + g;
                const char* pw = smem + OFF_WH + n * ROWB + (kb + tt * 2) * 2;
                bh[nb][0] = *(const uint32_t*)pw;
                bh[nb][1] = *(const uint32_t*)(pw + 16);
                const char* pl = pw + (OFF_WL - OFF_WH);
                bl[nb][0] = *(const uint32_t*)pl;
                bl[nb][1] = *(const uint32_t*)(pl + 16);
            }
#pragma unroll
            for (int mb = 0; mb < 4; ++mb) {
                int r = wm * 64 + mb * 16 + g;
                const char* pa = smem + OFF_AH + r * ROWB + (kb + tt * 2) * 2;
                uint32_t ah0 = *(const uint32_t*)pa;
                uint32_t ah1 = *(const uint32_t*)(pa + 8 * ROWB);
                uint32_t ah2 = *(const uint32_t*)(pa + 16);
                uint32_t ah3 = *(const uint32_t*)(pa + 8 * ROWB + 16);
                const char* pal = pa + (OFF_AL - OFF_AH);
                uint32_t al0 = *(const uint32_t*)pal;
                uint32_t al1 = *(const uint32_t*)(pal + 8 * ROWB);
                uint32_t al2 = *(const uint32_t*)(pal + 16);
                uint32_t al3 = *(const uint32_t*)(pal + 8 * ROWB + 16);
#pragma unroll
                for (int nb = 0; nb < 4; ++nb) {
                    HMMA(c[mb][nb], ah0, ah1, ah2, ah3, bh[nb][0], bh[nb][1]);
                    HMMA(c[mb][nb], ah0, ah1, ah2, ah3, bl[nb][0], bl[nb][1]);
                    HMMA(c[mb][nb], al0, al1, al2, al3, bh[nb][0], bh[nb][1]);
                }
            }
        }
        __syncthreads();
    }

    // spill C to smem (aliases A region), stride 129 floats
    float* Csm = (float*)smem;
#pragma unroll
    for (int mb = 0; mb < 4; ++mb) {
        int r0 = wm * 64 + mb * 16 + g;
#pragma unroll
        for (int nb = 0; nb < 4; ++nb) {
            int col = wn * 32 + nb * 8 + tt * 2;
            Csm[r0 * 129 + col]           = c[mb][nb][0];
            Csm[r0 * 129 + col + 1]       = c[mb][nb][1];
            Csm[(r0 + 8) * 129 + col]     = c[mb][nb][2];
            Csm[(r0 + 8) * 129 + col + 1] = c[mb][nb][3];
        }
    }
    __syncthreads();

    const float* bs = (const float*)(smem + OFF_BIAS);
    if (EPI == 2) {
        if (t < 128) {
            const float* crow = Csm + t * 129;
            float sum = 0.f, sq = 0.f;
#pragma unroll
            for (int j = 0; j < 128; ++j) {
                float x = crow[j] + bs[j];
                sum += x; sq += x * x;
            }
            float mean = sum * (1.f / 128.f);
            float var  = sq * (1.f / 128.f) - mean * mean;
            ((float*)(smem + OFF_MEAN))[t] = mean;
            ((float*)(smem + OFF_RSTD))[t] = rsqrtf(var + 1e-5f);
        }
        __syncthreads();
    }

    const float* gg = (const float*)(smem + OFF_G);
    const float* bb = (const float*)(smem + OFF_BETA);
    const float* mn = (const float*)(smem + OFF_MEAN);
    const float* rs = (const float*)(smem + OFF_RSTD);
    for (int i = t; i < 4096; i += 256) {
        int row = i >> 5, q = i & 31;
        int grow = tile0 + row;
        if (grow >= nrows) continue;
        int base = row * 129 + q * 4;
        float x0 = Csm[base + 0] + bs[q * 4 + 0];
        float x1 = Csm[base + 1] + bs[q * 4 + 1];
        float x2 = Csm[base + 2] + bs[q * 4 + 2];
        float x3 = Csm[base + 3] + bs[q * 4 + 3];
        float4 o;
        if (EPI == 2) {
            float mean = mn[row], rstd = rs[row];
            float4 r = *reinterpret_cast<const float4*>(resid + (size_t)grow * HH + q * 4);
            o.x = fmaxf((x0 - mean) * rstd * gg[q*4+0] + bb[q*4+0], 0.f) + r.x;
            o.y = fmaxf((x1 - mean) * rstd * gg[q*4+1] + bb[q*4+1], 0.f) + r.y;
            o.z = fmaxf((x2 - mean) * rstd * gg[q*4+2] + bb[q*4+2], 0.f) + r.z;
            o.w = fmaxf((x3 - mean) * rstd * gg[q*4+3] + bb[q*4+3], 0.f) + r.w;
        } else if (EPI == 1) {
            o.x = fmaxf(x0, 0.f); o.y = fmaxf(x1, 0.f);
            o.z = fmaxf(x2, 0.f); o.w = fmaxf(x3, 0.f);
        } else {
            o.x = x0; o.y = x1; o.z = x2; o.w = x3;
        }
        *reinterpret_cast<float4*>(out + (size_t)grow * HH + q * 4) = o;
    }
}

// ---------------- small helpers ----------------
__device__ __forceinline__ float warp_sum(float v) {
#pragma unroll
    for (int o = 16; o > 0; o >>= 1) v += __shfl_xor_sync(0xffffffffu, v, o);
    return v;
}

// ---------------- CSR build ----------------
__global__ void k_init() {
    int i = blockIdx.x * blockDim.x + threadIdx.x;
    if (i < NN) { g_deg[i] = 0; g_cur[i] = 0; }
}
__global__ void k_deg(const int* __restrict__ ei) {
    int e = blockIdx.x * blockDim.x + threadIdx.x;
    if (e < EE) atomicAdd(&g_deg[ei[EE + e]], 1);
}
__global__ void k_scan() {
    __shared__ int sm[1024];
    const int n = NN;
    const int chunk = (n + 1023) / 1024;
    int t = threadIdx.x;
    int base = t * chunk;
    int s = 0;
    for (int i = 0; i < chunk; ++i) {
        int idx = base + i;
        if (idx < n) s += g_deg[idx];
    }
    sm[t] = s;
    __syncthreads();
    for (int d = 1; d < 1024; d <<= 1) {
        int add = (t >= d) ? sm[t - d] : 0;
        __syncthreads();
        sm[t] += add;
        __syncthreads();
    }
    int run = sm[t] - s;
    for (int i = 0; i < chunk; ++i) {
        int idx = base + i;
        if (idx < n) { g_off[idx] = run; run += g_deg[idx]; }
    }
    if (t == 1023) g_off[n] = sm[1023];
}
__global__ void k_fill(const int* __restrict__ ei) {
    int e = blockIdx.x * blockDim.x + threadIdx.x;
    if (e < EE) {
        int s = ei[e];
        int d = ei[EE + e];
        int slot = atomicAdd(&g_cur[d], 1);
        g_col[g_off[d] + slot] = s;
    }
}

// ---------------- neighbor mean aggregation (warp per node) ----------------
__global__ void __launch_bounds__(256) k_aggr(const float* __restrict__ x) {
    int warp = (blockIdx.x * blockDim.x + threadIdx.x) >> 5;
    int lane = threadIdx.x & 31;
    if (warp >= NN) return;
    int s0 = g_off[warp], s1 = g_off[warp + 1];
    float4 a = make_float4(0.f, 0.f, 0.f, 0.f);
    for (int i = s0; i < s1; ++i) {
        int nb = __ldg(&g_col[i]);
        float4 xv = __ldg(reinterpret_cast<const float4*>(x + (size_t)nb * HH) + lane);
        a.x += xv.x; a.y += xv.y; a.z += xv.z; a.w += xv.w;
    }
    float inv = 1.f / fmaxf((float)(s1 - s0), 1.f);
    a.x *= inv; a.y *= inv; a.z *= inv; a.w *= inv;
    reinterpret_cast<float4*>(g_agg + (size_t)warp * HH)[lane] = a;
}

// ---------------- attention prep ----------------
__global__ void k_prep(const float* __restrict__ in_proj_W,
                       const float* __restrict__ in_proj_b,
                       const float* __restrict__ query) {
    __shared__ float qv[128];
    int t = threadIdx.x;
    float s = in_proj_b[t];
    for (int k = 0; k < 128; ++k) s = fmaf(in_proj_W[t * 128 + k], query[k], s);
    qv[t] = s;
    __syncthreads();
    const float inv = 1.0f / sqrtf(32.0f);
    float u[4] = {0.f, 0.f, 0.f, 0.f};
    for (int r = 0; r < 128; ++r) {
        float w = in_proj_W[(128 + r) * 128 + t];
        u[r >> 5] = fmaf(qv[r], w, u[r >> 5]);
    }
#pragma unroll
    for (int h = 0; h < 4; ++h) g_U[t * 4 + h] = u[h] * inv;
    if (t < 4) {
        float cc = 0.f;
        for (int d = 0; d < 32; ++d) cc = fmaf(qv[t * 32 + d], in_proj_b[128 + t * 32 + d], cc);
        g_cvec[t] = cc * inv;
    }
}

// ---------------- scores = x @ U + c ----------------
__global__ void __launch_bounds__(256) k_scores(const float* __restrict__ x) {
    int warp = (blockIdx.x * blockDim.x + threadIdx.x) >> 5;
    int lane = threadIdx.x & 31;
    if (warp >= NN) return;
    float4 xv = __ldg(reinterpret_cast<const float4*>(x + (size_t)warp * HH) + lane);
    float xs[4] = {xv.x, xv.y, xv.z, xv.w};
    float4 acc = make_float4(0.f, 0.f, 0.f, 0.f);
    const float4* U4 = reinterpret_cast<const float4*>(g_U);
#pragma unroll
    for (int s = 0; s < 4; ++s) {
        float4 u = U4[lane * 4 + s];
        acc.x = fmaf(xs[s], u.x, acc.x);
        acc.y = fmaf(xs[s], u.y, acc.y);
        acc.z = fmaf(xs[s], u.z, acc.z);
        acc.w = fmaf(xs[s], u.w, acc.w);
    }
    acc.x = warp_sum(acc.x); acc.y = warp_sum(acc.y);
    acc.z = warp_sum(acc.z); acc.w = warp_sum(acc.w);
    if (lane == 0) {
        float4 r;
        r.x = acc.x + g_cvec[0]; r.y = acc.y + g_cvec[1];
        r.z = acc.z + g_cvec[2]; r.w = acc.w + g_cvec[3];
        reinterpret_cast<float4*>(g_scores)[warp] = r;
    }
}

// ---------------- graph boundaries ----------------
__global__ void k_gbounds(const int* __restrict__ batch) {
    int i = blockIdx.x * blockDim.x + threadIdx.x;
    if (i >= NN) return;
    int bi = batch[i];
    if (i == 0) {
        for (int g = 0; g <= bi; ++g) g_gstart[g] = 0;
    } else {
        int bp = batch[i - 1];
        for (int g = bp + 1; g <= bi; ++g) g_gstart[g] = i;
    }
    if (i == NN - 1) {
        for (int g = bi + 1; g <= BB; ++g) g_gstart[g] = NN;
    }
}

// ---------------- per-graph softmax pool ----------------
__global__ void __launch_bounds__(256) k_pool() {
    int b = blockIdx.x;
    int s0 = g_gstart[b], s1 = g_gstart[b + 1];
    int t = threadIdx.x;
    __shared__ float4 red[256];
    __shared__ float smax[4];
    __shared__ float pbuf[256];
    __shared__ float dbuf[8];

    float4 mx = make_float4(-1e30f, -1e30f, -1e30f, -1e30f);
    for (int n = s0 + t; n < s1; n += 256) {
        float4 f = reinterpret_cast<const float4*>(g_scores)[n];
        mx.x = fmaxf(mx.x, f.x); mx.y = fmaxf(mx.y, f.y);
        mx.z = fmaxf(mx.z, f.z); mx.w = fmaxf(mx.w, f.w);
    }
    red[t] = mx;
    __syncthreads();
    for (int s = 128; s > 0; s >>= 1) {
        if (t < s) {
            float4 a = red[t], c = red[t + s];
            a.x = fmaxf(a.x, c.x); a.y = fmaxf(a.y, c.y);
            a.z = fmaxf(a.z, c.z); a.w = fmaxf(a.w, c.w);
            red[t] = a;
        }
        __syncthreads();
    }
    if (t == 0) { smax[0] = red[0].x; smax[1] = red[0].y; smax[2] = red[0].z; smax[3] = red[0].w; }
    __syncthreads();

    int tau = t >> 7, j = t & 127, h = j >> 5;
    float m = smax[h];
    float pl = 0.f, den = 0.f;
    for (int n = s0 + tau; n < s1; n += 2) {
        float e = expf(g_scores[n * 4 + h] - m);
        pl = fmaf(e, g_v[(size_t)n * HH + j], pl);
        den += e;
    }
    pbuf[t] = pl;
    if ((j & 31) == 0) dbuf[tau * 4 + h] = den;
    __syncthreads();
    if (t < 128) {
        float d = dbuf[h] + dbuf[4 + h];
        float p = pbuf[t] + pbuf[128 + t];
        g_pooled[b * HH + t] = (d > 0.f) ? p / d : 0.f;
    }
}

// ---------------- tail ----------------
__device__ __forceinline__ float block_ln128(float v, float gamma, float beta,
                                             float* ws, float* wq) {
    float s = warp_sum(v);
    float q = warp_sum(v * v);
    int wid = threadIdx.x >> 5, lane = threadIdx.x & 31;
    if (lane == 0) { ws[wid] = s; wq[wid] = q; }
    __syncthreads();
    float ts = ws[0] + ws[1] + ws[2] + ws[3];
    float tq = wq[0] + wq[1] + wq[2] + wq[3];
    __syncthreads();
    float mean = ts * (1.f / 128.f);
    float var  = tq * (1.f / 128.f) - mean * mean;
    return (v - mean) * rsqrtf(var + 1e-5f) * gamma + beta;
}

__global__ void __launch_bounds__(128) k_tail(
    const float* __restrict__ out_W, const float* __restrict__ out_b,
    const float* __restrict__ symfeat,
    const float* __restrict__ sym_W, const float* __restrict__ sym_b,
    const float* __restrict__ symf_W, const float* __restrict__ symf_b,
    const float* __restrict__ symf_g, const float* __restrict__ symf_beta,
    const float* __restrict__ fus_W, const float* __restrict__ fus_b,
    const float* __restrict__ fus_g, const float* __restrict__ fus_beta,
    const float* __restrict__ hW1, const float* __restrict__ hb1,
    const float* __restrict__ hW2, const float* __restrict__ hb2,
    float* __restrict__ outp)
{
    int b = blockIdx.x;
    int t = threadIdx.x;
    __shared__ float p[128];
    __shared__ float cat[256];
    __shared__ float buf[128];
    __shared__ float hh[192];
    __shared__ float ws[4], wq[4];

    p[t] = g_pooled[b * HH + t];
    __syncthreads();
    {
        float acc = out_b[t];
        for (int k = 0; k < 128; ++k) acc = fmaf(out_W[t * 128 + k], p[k], acc);
        cat[t] = acc;
    }
    {
        int f = t >> 5, o = t & 31;
        const float* sf = symfeat + b * 64 + f * 16;
        const float* w  = sym_W + (f * 32 + o) * 16;
        float s = sym_b[f * 32 + o];
#pragma unroll
        for (int i = 0; i < 16; ++i) s = fmaf(w[i], sf[i], s);
        buf[t] = fmaxf(s, 0.f);
    }
    __syncthreads();
    {
        float s2 = symf_b[t];
        for (int k = 0; k < 128; ++k) s2 = fmaf(symf_W[t * 128 + k], buf[k], s2);
        s2 = fmaxf(s2, 0.f);
        float v = block_ln128(s2, symf_g[t], symf_beta[t], ws, wq);
        cat[128 + t] = v;
    }
    __syncthreads();
    {
        float f = fus_b[t];
        for (int k = 0; k < 256; ++k) f = fmaf(fus_W[t * 256 + k], cat[k], f);
        f = fmaxf(f, 0.f);
        float v = block_ln128(f, fus_g[t], fus_beta[t], ws, wq);
        p[t] = v;
    }
    __syncthreads();
    for (int idx = t; idx < 192; idx += 128) {
        int k = idx >> 6, o = idx & 63;
        const float* w = hW1 + (size_t)(k * 64 + o) * 128;
        float acc = hb1[k * 64 + o];
        for (int j = 0; j < 128; ++j) acc = fmaf(w[j], p[j], acc);
        hh[idx] = fmaxf(acc, 0.f);
    }
    __syncthreads();
    if (t < 3) {
        float z = hb2[t];
        for (int o = 0; o < 64; ++o) z = fmaf(hW2[t * 64 + o], hh[t * 64 + o], z);
        outp[t * BB + b] = 1.f / (1.f + expf(-z));
    }
}

// ---------------- host ----------------
extern "C" void kernel_launch(void* const* d_in, const int* in_sizes, int n_in,
                              void* d_out, int out_size) {
    const float* nf = nullptr;
    const float* symf = nullptr;
    const int* ei = nullptr;
    const int* batch = nullptr;
    const float* P[26];
    int pi = 0;
    for (int i = 0; i < n_in; ++i) {
        int sz = in_sizes[i];
        if (sz == NN * HH)       nf    = (const float*)d_in[i];
        else if (sz == BB * 64)  symf  = (const float*)d_in[i];
        else if (sz == 2 * EE)   ei    = (const int*)d_in[i];
        else if (sz == NN)       batch = (const int*)d_in[i];
        else if (pi < 26)        P[pi++] = (const float*)d_in[i];
    }
    const float *W_in = P[0], *b_in = P[1], *sage_Wl = P[2], *sage_bl = P[3],
                *sage_Wr = P[4], *ln_g = P[5], *ln_b = P[6], *query = P[7],
                *in_proj_W = P[8], *in_proj_b = P[9], *out_W = P[10], *out_b = P[11],
                *sym_W = P[12], *sym_b = P[13], *symf_W = P[14], *symf_b = P[15],
                *symf_g = P[16], *symf_beta = P[17], *fus_W = P[18], *fus_b = P[19],
                *fus_g = P[20], *fus_beta = P[21], *hW1 = P[22], *hb1 = P[23],
                *hW2 = P[24], *hb2 = P[25];

    float *px, *px2, *pagg, *pv;
    cudaGetSymbolAddress((void**)&px,   g_x);
    cudaGetSymbolAddress((void**)&px2,  g_x2);
    cudaGetSymbolAddress((void**)&pagg, g_agg);
    cudaGetSymbolAddress((void**)&pv,   g_v);

    cudaFuncSetAttribute((const void*)k_mma<1, 0>, cudaFuncAttributeMaxDynamicSharedMemorySize, SMEM_BYTES);
    cudaFuncSetAttribute((const void*)k_mma<1, 1>, cudaFuncAttributeMaxDynamicSharedMemorySize, SMEM_BYTES);
    cudaFuncSetAttribute((const void*)k_mma<2, 2>, cudaFuncAttributeMaxDynamicSharedMemorySize, SMEM_BYTES);

    k_init<<<(NN + 255) / 256, 256>>>();
    k_deg<<<(EE + 255) / 256, 256>>>(ei);
    k_scan<<<1, 1024>>>();
    k_fill<<<(EE + 255) / 256, 256>>>(ei);
    k_prep<<<1, 128>>>(in_proj_W, in_proj_b, query);
    k_gbounds<<<(NN + 255) / 256, 256>>>(batch);
    // weight slots: 0=W_in, 1=Wl0, 2=Wr0, 3=Wl1, 4=Wr1, 5=Wl2, 6=Wr2, 7=Wv
    k_wconv<<<128, 256>>>(W_in,
                          sage_Wl + 0 * 16384, sage_Wr + 0 * 16384,
                          sage_Wl + 1 * 16384, sage_Wr + 1 * 16384,
                          sage_Wl + 2 * 16384, sage_Wr + 2 * 16384,
                          in_proj_W + 256 * 128);

    // x = relu(node_features @ W_in^T + b_in)
    k_mma<1, 1><<<TILES, 256, SMEM_BYTES>>>(nf, nullptr, 0, b_in,
                                            nullptr, nullptr, nullptr, px, NN);

    float* cur = px;
    float* nxt = px2;
    for (int l = 0; l < 3; ++l) {
        k_aggr<<<(NN * 32 + 255) / 256, 256>>>(cur);
        // h = agg@Wl^T + x@Wr^T + bias -> LN -> relu -> +x
        k_mma<2, 2><<<TILES, 256, SMEM_BYTES>>>(pagg, cur, 1 + 2 * l, sage_bl + l * 128,
                                                ln_g + l * 128, ln_b + l * 128, cur, nxt, NN);
        float* tmp = cur; cur = nxt; nxt = tmp;
    }

    // v = x @ Wv^T + bv
    k_mma<1, 0><<<TILES, 256, SMEM_BYTES>>>(cur, nullptr, 7, in_proj_b + 256,
                                            nullptr, nullptr, nullptr, pv, NN);

    k_scores<<<(NN * 32 + 255) / 256, 256>>>(cur);
    k_pool<<<BB, 256>>>();
    k_tail<<<BB, 128>>>(out_W, out_b, symf, sym_W, sym_b,
                        symf_W, symf_b, symf_g, symf_beta,
                        fus_W, fus_b, fus_g, fus_beta,
                        hW1, hb1, hW2, hb2, (float*)d_out);
    (void)out_size;
}